// round 9
// baseline (speedup 1.0000x reference)
#include <cuda_runtime.h>
#include <cuda_bf16.h>
#include <cuda_fp16.h>

#define BATCH 4
#define SEQ 4096
#define NH 6
#define HD 64
#define DIMC 384
#define BH (BATCH * NH)
#define MTOT (BATCH * SEQ)
#define SCALE_L2E 0.18033688011112042f  // 0.125 * log2(e)

// ---------------- device scratch ----------------
__device__ __nv_bfloat16 g_xhi[(size_t)MTOT * DIMC], g_xlo[(size_t)MTOT * DIMC];
__device__ __nv_bfloat16 g_wqt_hi[(size_t)3 * DIMC * DIMC], g_wqt_lo[(size_t)3 * DIMC * DIMC];
__device__ __nv_bfloat16 g_wpt_hi[(size_t)DIMC * DIMC], g_wpt_lo[(size_t)DIMC * DIMC];
__device__ __half        g_qh[(size_t)BH * SEQ * HD];           // single fp16, pre-scaled
__device__ __half        g_kh[(size_t)BH * SEQ * HD];           // single fp16
__device__ __half        g_vthi[(size_t)BH * HD * SEQ], g_vtlo[(size_t)BH * HD * SEQ];
__device__ __nv_bfloat16 g_ahi[(size_t)MTOT * DIMC], g_alo[(size_t)MTOT * DIMC];

// ---------------- helpers ----------------
__device__ __forceinline__ unsigned su32(const void* p) {
    unsigned a;
    asm("{ .reg .u64 t; cvta.to.shared.u64 t, %1; cvt.u32.u64 %0, t; }" : "=r"(a) : "l"(p));
    return a;
}
#define SW(o) ((o) ^ (((o) >> 3) & 0x70))

__device__ __forceinline__ void ldsm4(unsigned* r, unsigned a) {
    asm volatile("ldmatrix.sync.aligned.m8n8.x4.shared.b16 {%0,%1,%2,%3}, [%4];"
                 : "=r"(r[0]), "=r"(r[1]), "=r"(r[2]), "=r"(r[3]) : "r"(a));
}
__device__ __forceinline__ void mma_bf(float* d, const unsigned* a, const unsigned* b) {
    asm volatile("mma.sync.aligned.m16n8k16.row.col.f32.bf16.bf16.f32 "
                 "{%0,%1,%2,%3}, {%4,%5,%6,%7}, {%8,%9}, {%0,%1,%2,%3};"
                 : "+f"(d[0]), "+f"(d[1]), "+f"(d[2]), "+f"(d[3])
                 : "r"(a[0]), "r"(a[1]), "r"(a[2]), "r"(a[3]), "r"(b[0]), "r"(b[1]));
}
__device__ __forceinline__ void mma_fp(float* d, const unsigned* a, const unsigned* b) {
    asm volatile("mma.sync.aligned.m16n8k16.row.col.f32.f16.f16.f32 "
                 "{%0,%1,%2,%3}, {%4,%5,%6,%7}, {%8,%9}, {%0,%1,%2,%3};"
                 : "+f"(d[0]), "+f"(d[1]), "+f"(d[2]), "+f"(d[3])
                 : "r"(a[0]), "r"(a[1]), "r"(a[2]), "r"(a[3]), "r"(b[0]), "r"(b[1]));
}
__device__ __forceinline__ float ex2f(float x) {
    float r; asm("ex2.approx.ftz.f32 %0, %1;" : "=f"(r) : "f"(x)); return r;
}
// bf16 truncation split of a pair: hi packed via prmt, lo = rn(residual) pair
__device__ __forceinline__ void split2(float a, float b, unsigned& hi, unsigned& lo) {
    float af = __uint_as_float(__float_as_uint(a) & 0xFFFF0000u);
    float bf_ = __uint_as_float(__float_as_uint(b) & 0xFFFF0000u);
    asm("prmt.b32 %0, %1, %2, 0x7632;"
        : "=r"(hi) : "r"(__float_as_uint(a)), "r"(__float_as_uint(b)));
    asm("cvt.rn.bf16x2.f32 %0, %1, %2;" : "=r"(lo) : "f"(b - bf_), "f"(a - af));
}
// fp16 rn split of a pair (lo half of word = a, hi half = b)
__device__ __forceinline__ void hsplit2(float a, float b, unsigned& hi, unsigned& lo) {
    asm("cvt.rn.f16x2.f32 %0, %1, %2;" : "=r"(hi) : "f"(b), "f"(a));
    __half2 hv = *(__half2*)&hi;
    float ra = a - __low2float(hv), rb = b - __high2float(hv);
    asm("cvt.rn.f16x2.f32 %0, %1, %2;" : "=r"(lo) : "f"(rb), "f"(ra));
}
__device__ __forceinline__ unsigned hpack(float a, float b) {  // lo=a hi=b
    unsigned r; asm("cvt.rn.f16x2.f32 %0, %1, %2;" : "=r"(r) : "f"(b), "f"(a)); return r;
}
__device__ __forceinline__ void fsplit(float x, __nv_bfloat16& h, __nv_bfloat16& l) {
    h = __float2bfloat16_rn(x);
    l = __float2bfloat16_rn(x - __bfloat162float(h));
}
__device__ __forceinline__ void cpa16(unsigned d, const void* s) {
    asm volatile("cp.async.cg.shared.global [%0], [%1], 16;" :: "r"(d), "l"(s) : "memory");
}
#define CPC()  asm volatile("cp.async.commit_group;" ::: "memory")
#define CPW0() asm volatile("cp.async.wait_group 0;" ::: "memory")

// ---------------- prep (cold) ----------------
__global__ void split_plain(const float* __restrict__ s, __nv_bfloat16* __restrict__ hi,
                            __nv_bfloat16* __restrict__ lo, int n) {
    int i = blockIdx.x * blockDim.x + threadIdx.x;
    if (i < n) { __nv_bfloat16 h, l; fsplit(s[i], h, l); hi[i] = h; lo[i] = l; }
}
__global__ void split_wT(const float* __restrict__ w, __nv_bfloat16* __restrict__ hi,
                         __nv_bfloat16* __restrict__ lo, int K, int N) {
    int i = blockIdx.x * blockDim.x + threadIdx.x;
    if (i < K * N) {
        int n = i / K, k = i - n * K;
        __nv_bfloat16 h, l; fsplit(w[(size_t)k * N + n], h, l);
        hi[i] = h; lo[i] = l;
    }
}

// ---------------- bf16x3 GEMM, cp.async double-buffered ----------------
// Tile 128x128, BK=32, 12 stages. MODE 0: fused qkv epilogue (q/k single fp16,
// q pre-scaled; V transposed via smem, fp16 hi/lo). MODE 1: bias + fp32 out.
template<int MODE>
__global__ __launch_bounds__(256, 2) void gemm_mma(
    const __nv_bfloat16* __restrict__ Ah, const __nv_bfloat16* __restrict__ Al,
    const __nv_bfloat16* __restrict__ Bh, const __nv_bfloat16* __restrict__ Bl,
    float* __restrict__ C, const float* __restrict__ bias, int ldc) {
    extern __shared__ char dsm[];
    unsigned AB = (su32(dsm) + 127) & ~127u;
    const int tid = threadIdx.x, lane = tid & 31, wid = tid >> 5;
    const int wm = wid >> 2, wn = wid & 3;
    const int n0 = blockIdx.x << 7, m0 = blockIdx.y << 7;
    float acc[4][4][4] = {};

    auto ldstage = [&](int s) {
        unsigned base = AB + (s & 1) * 40960;
        #pragma unroll
        for (int k = 0; k < 2; k++) {
            int idx = tid + k * 256;
            int row = idx >> 2, c = idx & 3;
            unsigned so = base + row * 80 + c * 16;
            size_t ga = (size_t)(m0 + row) * DIMC + s * 32 + c * 8;
            size_t gb = (size_t)(n0 + row) * DIMC + s * 32 + c * 8;
            cpa16(so,         Ah + ga);
            cpa16(so + 10240, Al + ga);
            cpa16(so + 20480, Bh + gb);
            cpa16(so + 30720, Bl + gb);
        }
        CPC();
    };

    ldstage(0);
    for (int s = 0; s < 12; s++) {
        CPW0();
        __syncthreads();
        if (s + 1 < 12) ldstage(s + 1);
        unsigned sAh = AB + (s & 1) * 40960;
        unsigned sAl = sAh + 10240, sBh = sAh + 20480, sBl = sAh + 30720;

        #pragma unroll
        for (int h2 = 0; h2 < 2; h2++) {
            unsigned ah[4][4], al[4][4], bh[4][2], bl[4][2], t4[4];
            #pragma unroll
            for (int mt = 0; mt < 4; mt++) {
                unsigned off = (unsigned)((wm * 64 + mt * 16 + (lane & 15)) * 80 +
                                          h2 * 32 + ((lane >> 4) << 4));
                ldsm4(ah[mt], sAh + off);
                ldsm4(al[mt], sAl + off);
            }
            #pragma unroll
            for (int sub = 0; sub < 2; sub++) {
                unsigned off = (unsigned)((wn * 32 + sub * 16 + (lane & 7) +
                                           ((lane >> 4) << 3)) * 80 +
                                          h2 * 32 + (((lane >> 3) & 1) << 4));
                ldsm4(t4, sBh + off);
                bh[2 * sub][0] = t4[0]; bh[2 * sub][1] = t4[1];
                bh[2 * sub + 1][0] = t4[2]; bh[2 * sub + 1][1] = t4[3];
                ldsm4(t4, sBl + off);
                bl[2 * sub][0] = t4[0]; bl[2 * sub][1] = t4[1];
                bl[2 * sub + 1][0] = t4[2]; bl[2 * sub + 1][1] = t4[3];
            }
            #pragma unroll
            for (int mt = 0; mt < 4; mt++)
                #pragma unroll
                for (int nt = 0; nt < 4; nt++) {
                    mma_bf(acc[mt][nt], ah[mt], bh[nt]);
                    mma_bf(acc[mt][nt], ah[mt], bl[nt]);
                    mma_bf(acc[mt][nt], al[mt], bh[nt]);
                }
        }
    }

    if (MODE == 1) {
        #pragma unroll
        for (int mt = 0; mt < 4; mt++) {
            int r0 = m0 + wm * 64 + mt * 16 + (lane >> 2);
            #pragma unroll
            for (int nt = 0; nt < 4; nt++) {
                int c0 = n0 + wn * 32 + nt * 8 + (lane & 3) * 2;
                float b0 = bias[c0], b1 = bias[c0 + 1];
                *(float2*)&C[(size_t)r0 * ldc + c0] =
                    make_float2(acc[mt][nt][0] + b0, acc[mt][nt][1] + b1);
                *(float2*)&C[(size_t)(r0 + 8) * ldc + c0] =
                    make_float2(acc[mt][nt][2] + b0, acc[mt][nt][3] + b1);
            }
        }
    } else {
        const int sect = n0 / 384;            // 0=q 1=k 2=v
        const int csec = n0 - sect * 384;
        const int b = m0 >> 12;
        const int tokb = m0 & 4095;
        if (sect < 2) {
            const float scl = (sect == 0) ? SCALE_L2E : 1.f;
            __half* G = (sect == 0) ? g_qh : g_kh;
            #pragma unroll
            for (int mt = 0; mt < 4; mt++) {
                int tok = tokb + wm * 64 + mt * 16 + (lane >> 2);
                #pragma unroll
                for (int nt = 0; nt < 4; nt++) {
                    int gcl = csec + wn * 32 + nt * 8 + (lane & 3) * 2;
                    int head = gcl >> 6, d = gcl & 63;
                    size_t ad = ((size_t)(b * NH + head) * SEQ + tok) * HD + d;
                    *(unsigned*)(G + ad) = hpack(acc[mt][nt][0] * scl, acc[mt][nt][1] * scl);
                    *(unsigned*)(G + ad + (size_t)8 * HD) =
                        hpack(acc[mt][nt][2] * scl, acc[mt][nt][3] * scl);
                }
            }
        } else {
            // V: transpose through smem (fp32 [col][tok], pad 132), emit fp16 hi/lo
            float* sT = (float*)(dsm + (AB - su32(dsm)));
            __syncthreads();
            #pragma unroll
            for (int mt = 0; mt < 4; mt++) {
                int tokl = wm * 64 + mt * 16 + (lane >> 2);
                #pragma unroll
                for (int nt = 0; nt < 4; nt++) {
                    int cl = wn * 32 + nt * 8 + (lane & 3) * 2;
                    sT[cl * 132 + tokl]           = acc[mt][nt][0];
                    sT[(cl + 1) * 132 + tokl]     = acc[mt][nt][1];
                    sT[cl * 132 + tokl + 8]       = acc[mt][nt][2];
                    sT[(cl + 1) * 132 + tokl + 8] = acc[mt][nt][3];
                }
            }
            __syncthreads();
            int cl = tid >> 1, hf = tid & 1;
            int gcl = csec + cl, head = gcl >> 6, d = gcl & 63;
            size_t vbase = ((size_t)(b * NH + head) * HD + d) * SEQ + tokb + hf * 64;
            #pragma unroll
            for (int j = 0; j < 64; j += 8) {
                float4 x0 = *(float4*)&sT[cl * 132 + hf * 64 + j];
                float4 x1 = *(float4*)&sT[cl * 132 + hf * 64 + j + 4];
                unsigned hb[4], lb[4];
                hsplit2(x0.x, x0.y, hb[0], lb[0]);
                hsplit2(x0.z, x0.w, hb[1], lb[1]);
                hsplit2(x1.x, x1.y, hb[2], lb[2]);
                hsplit2(x1.z, x1.w, hb[3], lb[3]);
                *(uint4*)(g_vthi + vbase + j) = *(uint4*)hb;
                *(uint4*)(g_vtlo + vbase + j) = *(uint4*)lb;
            }
        }
    }
}

// ---------------- attention: fp16 single QK, fp16 single P, fp16 hi/lo V ----------------
// smem: Q (fp16, 128x64, 16KB) @AB; KV @AB+16384: 2 bufs x 24KB {k 8KB, vh 8KB, vl 8KB}
__global__ __launch_bounds__(256, 2) void attn_mma() {
    extern __shared__ char dsm[];
    unsigned AB = (su32(dsm) + 1023) & ~1023u;
    char* sb = dsm + (AB - su32(dsm));
    const int tid = threadIdx.x, lane = tid & 31, wm = tid >> 5;
    const int q0 = blockIdx.x << 7;
    const int bh_ = blockIdx.y, b = bh_ / NH, h = bh_ % NH;
    const unsigned QB = AB, KV = AB + 16384;

    {   // load Q 128x64 fp16
        int row = tid >> 1, half = tid & 1;
        size_t g = ((size_t)bh_ * SEQ + q0 + row) * HD + half * 32;
        #pragma unroll
        for (int cc = 0; cc < 4; cc++) {
            unsigned o = SW((unsigned)(row * 128 + half * 64 + cc * 16));
            *(uint4*)(sb + o) = *(const uint4*)(g_qh + g + cc * 8);
        }
    }

    auto ldkv = [&](int t, int bi) {
        unsigned nb = KV + bi * 24576;
        #pragma unroll
        for (int k = 0; k < 2; k++) {
            int idx = tid + k * 256;       // 0..511
            int row = idx >> 3, c = idx & 7;
            unsigned o = SW((unsigned)(row * 128 + c * 16));
            cpa16(nb + o, g_kh + ((size_t)bh_ * SEQ + t * 64 + row) * HD + c * 8);
            size_t gv = ((size_t)bh_ * HD + row) * SEQ + t * 64 + c * 8;
            cpa16(nb + 8192 + o,  g_vthi + gv);
            cpa16(nb + 16384 + o, g_vtlo + gv);
        }
        CPC();
    };
    ldkv(0, 0);
    __syncthreads();

    float oacc[8][4] = {};
    float l0 = 0.f, l1 = 0.f;

    for (int t = 0; t < 64; t++) {
        int bi = t & 1;
        unsigned kb = KV + bi * 24576, vb = kb + 8192;
        CPW0();
        __syncthreads();
        if (t + 1 < 64) ldkv(t + 1, bi ^ 1);

        // S = Q @ K^T  (fp16 x fp16, single product)
        float sacc[8][4] = {};
        #pragma unroll
        for (int s = 0; s < 4; s++) {
            unsigned qf[4];
            unsigned oq = SW((unsigned)((wm * 16 + (lane & 15)) * 128 + s * 32 +
                                        ((lane >> 4) << 4)));
            ldsm4(qf, QB + oq);
            #pragma unroll
            for (int sub = 0; sub < 4; sub++) {
                unsigned kf[4];
                unsigned ok = SW((unsigned)((sub * 16 + (lane & 7) + ((lane >> 4) << 3)) * 128 +
                                            s * 32 + (((lane >> 3) & 1) << 4)));
                ldsm4(kf, kb + ok);
                mma_fp(sacc[2 * sub],     qf, kf);
                mma_fp(sacc[2 * sub + 1], qf, kf + 2);
            }
        }

        // softmax -> single-fp16 P A-fragments
        unsigned pp[4][4];
        #pragma unroll
        for (int nt = 0; nt < 8; nt++) {
            float p0 = ex2f(sacc[nt][0]), p1 = ex2f(sacc[nt][1]);
            float p2 = ex2f(sacc[nt][2]), p3 = ex2f(sacc[nt][3]);
            l0 += p0 + p1; l1 += p2 + p3;
            int s = nt >> 1, hf = (nt & 1) * 2;
            pp[s][hf]     = hpack(p0, p1);
            pp[s][hf + 1] = hpack(p2, p3);
        }

        // O += P @ Vt^T  (fp16, 2 products: vh + vl)
        #pragma unroll
        for (int s = 0; s < 4; s++) {
            #pragma unroll
            for (int sp = 0; sp < 2; sp++) {
                unsigned vfh[2][4], vfl[2][4];
                #pragma unroll
                for (int u = 0; u < 2; u++) {
                    int sub = sp * 2 + u;
                    unsigned ov = SW((unsigned)((sub * 16 + (lane & 7) + ((lane >> 4) << 3)) * 128 +
                                                s * 32 + (((lane >> 3) & 1) << 4)));
                    ldsm4(vfh[u], vb + ov);
                    ldsm4(vfl[u], vb + 8192 + ov);
                }
                #pragma unroll
                for (int u = 0; u < 2; u++) {
                    mma_fp(oacc[2 * (sp * 2 + u)],     pp[s], vfh[u]);
                    mma_fp(oacc[2 * (sp * 2 + u) + 1], pp[s], vfh[u] + 2);
                }
                #pragma unroll
                for (int u = 0; u < 2; u++) {
                    mma_fp(oacc[2 * (sp * 2 + u)],     pp[s], vfl[u]);
                    mma_fp(oacc[2 * (sp * 2 + u) + 1], pp[s], vfl[u] + 2);
                }
            }
        }
    }

    l0 += __shfl_xor_sync(0xffffffffu, l0, 1);
    l0 += __shfl_xor_sync(0xffffffffu, l0, 2);
    l1 += __shfl_xor_sync(0xffffffffu, l1, 1);
    l1 += __shfl_xor_sync(0xffffffffu, l1, 2);
    float i0 = 1.f / l0, i1 = 1.f / l1;

    int r = wm * 16 + (lane >> 2);
    #pragma unroll
    for (int nt = 0; nt < 8; nt++) {
        int c = nt * 8 + (lane & 3) * 2;
        size_t ob = ((size_t)b * SEQ + q0 + r) * DIMC + h * HD + c;
        unsigned hw, lw;
        split2(oacc[nt][0] * i0, oacc[nt][1] * i0, hw, lw);
        *(unsigned*)(g_ahi + ob) = hw;
        *(unsigned*)(g_alo + ob) = lw;
        split2(oacc[nt][2] * i1, oacc[nt][3] * i1, hw, lw);
        *(unsigned*)(g_ahi + ob + (size_t)8 * DIMC) = hw;
        *(unsigned*)(g_alo + ob + (size_t)8 * DIMC) = lw;
    }
}

// ---------------- host ----------------
extern "C" void kernel_launch(void* const* d_in, const int* in_sizes, int n_in,
                              void* d_out, int out_size) {
    const float* x      = (const float*)d_in[0];
    const float* w_qkv  = (const float*)d_in[1];
    const float* w_proj = (const float*)d_in[2];
    const float* b_proj = (const float*)d_in[3];
    float* out = (float*)d_out;

    __nv_bfloat16 *xhi, *xlo, *wqh, *wql, *wph, *wpl, *ahi, *alo;
    cudaGetSymbolAddress((void**)&xhi, g_xhi);    cudaGetSymbolAddress((void**)&xlo, g_xlo);
    cudaGetSymbolAddress((void**)&wqh, g_wqt_hi); cudaGetSymbolAddress((void**)&wql, g_wqt_lo);
    cudaGetSymbolAddress((void**)&wph, g_wpt_hi); cudaGetSymbolAddress((void**)&wpl, g_wpt_lo);
    cudaGetSymbolAddress((void**)&ahi, g_ahi);    cudaGetSymbolAddress((void**)&alo, g_alo);

    const int GEMM_SMEM = 2 * 40960 + 256;          // 82176
    const int ATTN_SMEM = 16384 + 2 * 24576 + 1024; // 66560
    cudaFuncSetAttribute(gemm_mma<0>, cudaFuncAttributeMaxDynamicSharedMemorySize, GEMM_SMEM);
    cudaFuncSetAttribute(gemm_mma<1>, cudaFuncAttributeMaxDynamicSharedMemorySize, GEMM_SMEM);
    cudaFuncSetAttribute(attn_mma, cudaFuncAttributeMaxDynamicSharedMemorySize, ATTN_SMEM);

    int nx = MTOT * DIMC;
    split_plain<<<(nx + 255) / 256, 256>>>(x, xhi, xlo, nx);
    split_wT<<<(3 * DIMC * DIMC + 255) / 256, 256>>>(w_qkv, wqh, wql, DIMC, 3 * DIMC);
    split_wT<<<(DIMC * DIMC + 255) / 256, 256>>>(w_proj, wph, wpl, DIMC, DIMC);

    gemm_mma<0><<<dim3(9, 128), 256, GEMM_SMEM>>>(xhi, xlo, wqh, wql, nullptr, nullptr, 0);
    attn_mma<<<dim3(SEQ / 128, BH), 256, ATTN_SMEM>>>();
    gemm_mma<1><<<dim3(3, 128), 256, GEMM_SMEM>>>(ahi, alo, wph, wpl, out, b_proj, DIMC);
}

// round 10
// speedup vs baseline: 1.0002x; 1.0002x over previous
#include <cuda_runtime.h>
#include <cuda_bf16.h>
#include <cuda_fp16.h>

#define BATCH 4
#define SEQ 4096
#define NH 6
#define HD 64
#define DIMC 384
#define BH (BATCH * NH)
#define MTOT (BATCH * SEQ)
#define SCALE_L2E 0.18033688011112042f  // 0.125 * log2(e)

// ---------------- device scratch ----------------
__device__ __nv_bfloat16 g_xhi[(size_t)MTOT * DIMC], g_xlo[(size_t)MTOT * DIMC];
__device__ __nv_bfloat16 g_wqt_hi[(size_t)3 * DIMC * DIMC], g_wqt_lo[(size_t)3 * DIMC * DIMC];
__device__ __nv_bfloat16 g_wpt_hi[(size_t)DIMC * DIMC], g_wpt_lo[(size_t)DIMC * DIMC];
__device__ __half        g_qh[(size_t)BH * SEQ * HD];           // single fp16, pre-scaled
__device__ __half        g_kh[(size_t)BH * SEQ * HD];           // single fp16
__device__ __half        g_vthi[(size_t)BH * HD * SEQ], g_vtlo[(size_t)BH * HD * SEQ];
__device__ __nv_bfloat16 g_ahi[(size_t)MTOT * DIMC], g_alo[(size_t)MTOT * DIMC];

// ---------------- helpers ----------------
__device__ __forceinline__ unsigned su32(const void* p) {
    unsigned a;
    asm("{ .reg .u64 t; cvta.to.shared.u64 t, %1; cvt.u32.u64 %0, t; }" : "=r"(a) : "l"(p));
    return a;
}
#define SW(o) ((o) ^ (((o) >> 3) & 0x70))

__device__ __forceinline__ void ldsm4(unsigned* r, unsigned a) {
    asm volatile("ldmatrix.sync.aligned.m8n8.x4.shared.b16 {%0,%1,%2,%3}, [%4];"
                 : "=r"(r[0]), "=r"(r[1]), "=r"(r[2]), "=r"(r[3]) : "r"(a));
}
__device__ __forceinline__ void mma_bf(float* d, const unsigned* a, const unsigned* b) {
    asm volatile("mma.sync.aligned.m16n8k16.row.col.f32.bf16.bf16.f32 "
                 "{%0,%1,%2,%3}, {%4,%5,%6,%7}, {%8,%9}, {%0,%1,%2,%3};"
                 : "+f"(d[0]), "+f"(d[1]), "+f"(d[2]), "+f"(d[3])
                 : "r"(a[0]), "r"(a[1]), "r"(a[2]), "r"(a[3]), "r"(b[0]), "r"(b[1]));
}
__device__ __forceinline__ void mma_fp(float* d, const unsigned* a, const unsigned* b) {
    asm volatile("mma.sync.aligned.m16n8k16.row.col.f32.f16.f16.f32 "
                 "{%0,%1,%2,%3}, {%4,%5,%6,%7}, {%8,%9}, {%0,%1,%2,%3};"
                 : "+f"(d[0]), "+f"(d[1]), "+f"(d[2]), "+f"(d[3])
                 : "r"(a[0]), "r"(a[1]), "r"(a[2]), "r"(a[3]), "r"(b[0]), "r"(b[1]));
}
__device__ __forceinline__ float ex2f(float x) {
    float r; asm("ex2.approx.ftz.f32 %0, %1;" : "=f"(r) : "f"(x)); return r;
}
// bf16 truncation split of a pair: hi packed via prmt, lo = rn(residual) pair
__device__ __forceinline__ void split2(float a, float b, unsigned& hi, unsigned& lo) {
    float af = __uint_as_float(__float_as_uint(a) & 0xFFFF0000u);
    float bf_ = __uint_as_float(__float_as_uint(b) & 0xFFFF0000u);
    asm("prmt.b32 %0, %1, %2, 0x7632;"
        : "=r"(hi) : "r"(__float_as_uint(a)), "r"(__float_as_uint(b)));
    asm("cvt.rn.bf16x2.f32 %0, %1, %2;" : "=r"(lo) : "f"(b - bf_), "f"(a - af));
}
// fp16 rn split of a pair (lo half of word = a, hi half = b)
__device__ __forceinline__ void hsplit2(float a, float b, unsigned& hi, unsigned& lo) {
    asm("cvt.rn.f16x2.f32 %0, %1, %2;" : "=r"(hi) : "f"(b), "f"(a));
    __half2 hv = *(__half2*)&hi;
    float ra = a - __low2float(hv), rb = b - __high2float(hv);
    asm("cvt.rn.f16x2.f32 %0, %1, %2;" : "=r"(lo) : "f"(rb), "f"(ra));
}
__device__ __forceinline__ unsigned hpack(float a, float b) {  // lo=a hi=b
    unsigned r; asm("cvt.rn.f16x2.f32 %0, %1, %2;" : "=r"(r) : "f"(b), "f"(a)); return r;
}
__device__ __forceinline__ void fsplit(float x, __nv_bfloat16& h, __nv_bfloat16& l) {
    h = __float2bfloat16_rn(x);
    l = __float2bfloat16_rn(x - __bfloat162float(h));
}
__device__ __forceinline__ void cpa16(unsigned d, const void* s) {
    asm volatile("cp.async.cg.shared.global [%0], [%1], 16;" :: "r"(d), "l"(s) : "memory");
}
#define CPC()  asm volatile("cp.async.commit_group;" ::: "memory")
#define CPW0() asm volatile("cp.async.wait_group 0;" ::: "memory")

// ---------------- prep (cold) ----------------
__global__ void split_plain(const float* __restrict__ s, __nv_bfloat16* __restrict__ hi,
                            __nv_bfloat16* __restrict__ lo, int n) {
    int i = blockIdx.x * blockDim.x + threadIdx.x;
    if (i < n) { __nv_bfloat16 h, l; fsplit(s[i], h, l); hi[i] = h; lo[i] = l; }
}
__global__ void split_wT(const float* __restrict__ w, __nv_bfloat16* __restrict__ hi,
                         __nv_bfloat16* __restrict__ lo, int K, int N) {
    int i = blockIdx.x * blockDim.x + threadIdx.x;
    if (i < K * N) {
        int n = i / K, k = i - n * K;
        __nv_bfloat16 h, l; fsplit(w[(size_t)k * N + n], h, l);
        hi[i] = h; lo[i] = l;
    }
}

// ---------------- bf16x3 GEMM, cp.async double-buffered ----------------
// Tile 128x128, BK=32, 12 stages. MODE 0: fused qkv epilogue (q/k single fp16,
// q pre-scaled; V transposed via smem, fp16 hi/lo). MODE 1: bias + fp32 out.
template<int MODE>
__global__ __launch_bounds__(256, 2) void gemm_mma(
    const __nv_bfloat16* __restrict__ Ah, const __nv_bfloat16* __restrict__ Al,
    const __nv_bfloat16* __restrict__ Bh, const __nv_bfloat16* __restrict__ Bl,
    float* __restrict__ C, const float* __restrict__ bias, int ldc) {
    extern __shared__ char dsm[];
    unsigned AB = (su32(dsm) + 127) & ~127u;
    const int tid = threadIdx.x, lane = tid & 31, wid = tid >> 5;
    const int wm = wid >> 2, wn = wid & 3;
    const int n0 = blockIdx.x << 7, m0 = blockIdx.y << 7;
    float acc[4][4][4] = {};

    auto ldstage = [&](int s) {
        unsigned base = AB + (s & 1) * 40960;
        #pragma unroll
        for (int k = 0; k < 2; k++) {
            int idx = tid + k * 256;
            int row = idx >> 2, c = idx & 3;
            unsigned so = base + row * 80 + c * 16;
            size_t ga = (size_t)(m0 + row) * DIMC + s * 32 + c * 8;
            size_t gb = (size_t)(n0 + row) * DIMC + s * 32 + c * 8;
            cpa16(so,         Ah + ga);
            cpa16(so + 10240, Al + ga);
            cpa16(so + 20480, Bh + gb);
            cpa16(so + 30720, Bl + gb);
        }
        CPC();
    };

    ldstage(0);
    for (int s = 0; s < 12; s++) {
        CPW0();
        __syncthreads();
        if (s + 1 < 12) ldstage(s + 1);
        unsigned sAh = AB + (s & 1) * 40960;
        unsigned sAl = sAh + 10240, sBh = sAh + 20480, sBl = sAh + 30720;

        #pragma unroll
        for (int h2 = 0; h2 < 2; h2++) {
            unsigned ah[4][4], al[4][4], bh[4][2], bl[4][2], t4[4];
            #pragma unroll
            for (int mt = 0; mt < 4; mt++) {
                unsigned off = (unsigned)((wm * 64 + mt * 16 + (lane & 15)) * 80 +
                                          h2 * 32 + ((lane >> 4) << 4));
                ldsm4(ah[mt], sAh + off);
                ldsm4(al[mt], sAl + off);
            }
            #pragma unroll
            for (int sub = 0; sub < 2; sub++) {
                unsigned off = (unsigned)((wn * 32 + sub * 16 + (lane & 7) +
                                           ((lane >> 4) << 3)) * 80 +
                                          h2 * 32 + (((lane >> 3) & 1) << 4));
                ldsm4(t4, sBh + off);
                bh[2 * sub][0] = t4[0]; bh[2 * sub][1] = t4[1];
                bh[2 * sub + 1][0] = t4[2]; bh[2 * sub + 1][1] = t4[3];
                ldsm4(t4, sBl + off);
                bl[2 * sub][0] = t4[0]; bl[2 * sub][1] = t4[1];
                bl[2 * sub + 1][0] = t4[2]; bl[2 * sub + 1][1] = t4[3];
            }
            #pragma unroll
            for (int mt = 0; mt < 4; mt++)
                #pragma unroll
                for (int nt = 0; nt < 4; nt++) {
                    mma_bf(acc[mt][nt], ah[mt], bh[nt]);
                    mma_bf(acc[mt][nt], ah[mt], bl[nt]);
                    mma_bf(acc[mt][nt], al[mt], bh[nt]);
                }
        }
    }

    if (MODE == 1) {
        #pragma unroll
        for (int mt = 0; mt < 4; mt++) {
            int r0 = m0 + wm * 64 + mt * 16 + (lane >> 2);
            #pragma unroll
            for (int nt = 0; nt < 4; nt++) {
                int c0 = n0 + wn * 32 + nt * 8 + (lane & 3) * 2;
                float b0 = bias[c0], b1 = bias[c0 + 1];
                *(float2*)&C[(size_t)r0 * ldc + c0] =
                    make_float2(acc[mt][nt][0] + b0, acc[mt][nt][1] + b1);
                *(float2*)&C[(size_t)(r0 + 8) * ldc + c0] =
                    make_float2(acc[mt][nt][2] + b0, acc[mt][nt][3] + b1);
            }
        }
    } else {
        const int sect = n0 / 384;            // 0=q 1=k 2=v
        const int csec = n0 - sect * 384;
        const int b = m0 >> 12;
        const int tokb = m0 & 4095;
        if (sect < 2) {
            const float scl = (sect == 0) ? SCALE_L2E : 1.f;
            __half* G = (sect == 0) ? g_qh : g_kh;
            #pragma unroll
            for (int mt = 0; mt < 4; mt++) {
                int tok = tokb + wm * 64 + mt * 16 + (lane >> 2);
                #pragma unroll
                for (int nt = 0; nt < 4; nt++) {
                    int gcl = csec + wn * 32 + nt * 8 + (lane & 3) * 2;
                    int head = gcl >> 6, d = gcl & 63;
                    size_t ad = ((size_t)(b * NH + head) * SEQ + tok) * HD + d;
                    *(unsigned*)(G + ad) = hpack(acc[mt][nt][0] * scl, acc[mt][nt][1] * scl);
                    *(unsigned*)(G + ad + (size_t)8 * HD) =
                        hpack(acc[mt][nt][2] * scl, acc[mt][nt][3] * scl);
                }
            }
        } else {
            // V: transpose through smem (fp32 [col][tok], pad 132), emit fp16 hi/lo
            float* sT = (float*)(dsm + (AB - su32(dsm)));
            __syncthreads();
            #pragma unroll
            for (int mt = 0; mt < 4; mt++) {
                int tokl = wm * 64 + mt * 16 + (lane >> 2);
                #pragma unroll
                for (int nt = 0; nt < 4; nt++) {
                    int cl = wn * 32 + nt * 8 + (lane & 3) * 2;
                    sT[cl * 132 + tokl]           = acc[mt][nt][0];
                    sT[(cl + 1) * 132 + tokl]     = acc[mt][nt][1];
                    sT[cl * 132 + tokl + 8]       = acc[mt][nt][2];
                    sT[(cl + 1) * 132 + tokl + 8] = acc[mt][nt][3];
                }
            }
            __syncthreads();
            int cl = tid >> 1, hf = tid & 1;
            int gcl = csec + cl, head = gcl >> 6, d = gcl & 63;
            size_t vbase = ((size_t)(b * NH + head) * HD + d) * SEQ + tokb + hf * 64;
            #pragma unroll
            for (int j = 0; j < 64; j += 8) {
                float4 x0 = *(float4*)&sT[cl * 132 + hf * 64 + j];
                float4 x1 = *(float4*)&sT[cl * 132 + hf * 64 + j + 4];
                unsigned hb[4], lb[4];
                hsplit2(x0.x, x0.y, hb[0], lb[0]);
                hsplit2(x0.z, x0.w, hb[1], lb[1]);
                hsplit2(x1.x, x1.y, hb[2], lb[2]);
                hsplit2(x1.z, x1.w, hb[3], lb[3]);
                *(uint4*)(g_vthi + vbase + j) = *(uint4*)hb;
                *(uint4*)(g_vtlo + vbase + j) = *(uint4*)lb;
            }
        }
    }
}

// ---------------- attention: fp16 single QK, fp16 single P, fp16 hi/lo V ----------------
// smem: Q (fp16, 128x64, 16KB) @AB; KV @AB+16384: 2 bufs x 24KB {k 8KB, vh 8KB, vl 8KB}
__global__ __launch_bounds__(256, 2) void attn_mma() {
    extern __shared__ char dsm[];
    unsigned AB = (su32(dsm) + 1023) & ~1023u;
    char* sb = dsm + (AB - su32(dsm));
    const int tid = threadIdx.x, lane = tid & 31, wm = tid >> 5;
    const int q0 = blockIdx.x << 7;
    const int bh_ = blockIdx.y, b = bh_ / NH, h = bh_ % NH;
    const unsigned QB = AB, KV = AB + 16384;

    {   // load Q 128x64 fp16
        int row = tid >> 1, half = tid & 1;
        size_t g = ((size_t)bh_ * SEQ + q0 + row) * HD + half * 32;
        #pragma unroll
        for (int cc = 0; cc < 4; cc++) {
            unsigned o = SW((unsigned)(row * 128 + half * 64 + cc * 16));
            *(uint4*)(sb + o) = *(const uint4*)(g_qh + g + cc * 8);
        }
    }

    auto ldkv = [&](int t, int bi) {
        unsigned nb = KV + bi * 24576;
        #pragma unroll
        for (int k = 0; k < 2; k++) {
            int idx = tid + k * 256;       // 0..511
            int row = idx >> 3, c = idx & 7;
            unsigned o = SW((unsigned)(row * 128 + c * 16));
            cpa16(nb + o, g_kh + ((size_t)bh_ * SEQ + t * 64 + row) * HD + c * 8);
            size_t gv = ((size_t)bh_ * HD + row) * SEQ + t * 64 + c * 8;
            cpa16(nb + 8192 + o,  g_vthi + gv);
            cpa16(nb + 16384 + o, g_vtlo + gv);
        }
        CPC();
    };
    ldkv(0, 0);
    __syncthreads();

    float oacc[8][4] = {};
    float l0 = 0.f, l1 = 0.f;

    for (int t = 0; t < 64; t++) {
        int bi = t & 1;
        unsigned kb = KV + bi * 24576, vb = kb + 8192;
        CPW0();
        __syncthreads();
        if (t + 1 < 64) ldkv(t + 1, bi ^ 1);

        // S = Q @ K^T  (fp16 x fp16, single product)
        float sacc[8][4] = {};
        #pragma unroll
        for (int s = 0; s < 4; s++) {
            unsigned qf[4];
            unsigned oq = SW((unsigned)((wm * 16 + (lane & 15)) * 128 + s * 32 +
                                        ((lane >> 4) << 4)));
            ldsm4(qf, QB + oq);
            #pragma unroll
            for (int sub = 0; sub < 4; sub++) {
                unsigned kf[4];
                unsigned ok = SW((unsigned)((sub * 16 + (lane & 7) + ((lane >> 4) << 3)) * 128 +
                                            s * 32 + (((lane >> 3) & 1) << 4)));
                ldsm4(kf, kb + ok);
                mma_fp(sacc[2 * sub],     qf, kf);
                mma_fp(sacc[2 * sub + 1], qf, kf + 2);
            }
        }

        // softmax -> single-fp16 P A-fragments
        unsigned pp[4][4];
        #pragma unroll
        for (int nt = 0; nt < 8; nt++) {
            float p0 = ex2f(sacc[nt][0]), p1 = ex2f(sacc[nt][1]);
            float p2 = ex2f(sacc[nt][2]), p3 = ex2f(sacc[nt][3]);
            l0 += p0 + p1; l1 += p2 + p3;
            int s = nt >> 1, hf = (nt & 1) * 2;
            pp[s][hf]     = hpack(p0, p1);
            pp[s][hf + 1] = hpack(p2, p3);
        }

        // O += P @ Vt^T  (fp16, 2 products: vh + vl)
        #pragma unroll
        for (int s = 0; s < 4; s++) {
            #pragma unroll
            for (int sp = 0; sp < 2; sp++) {
                unsigned vfh[2][4], vfl[2][4];
                #pragma unroll
                for (int u = 0; u < 2; u++) {
                    int sub = sp * 2 + u;
                    unsigned ov = SW((unsigned)((sub * 16 + (lane & 7) + ((lane >> 4) << 3)) * 128 +
                                                s * 32 + (((lane >> 3) & 1) << 4)));
                    ldsm4(vfh[u], vb + ov);
                    ldsm4(vfl[u], vb + 8192 + ov);
                }
                #pragma unroll
                for (int u = 0; u < 2; u++) {
                    mma_fp(oacc[2 * (sp * 2 + u)],     pp[s], vfh[u]);
                    mma_fp(oacc[2 * (sp * 2 + u) + 1], pp[s], vfh[u] + 2);
                }
                #pragma unroll
                for (int u = 0; u < 2; u++) {
                    mma_fp(oacc[2 * (sp * 2 + u)],     pp[s], vfl[u]);
                    mma_fp(oacc[2 * (sp * 2 + u) + 1], pp[s], vfl[u] + 2);
                }
            }
        }
    }

    l0 += __shfl_xor_sync(0xffffffffu, l0, 1);
    l0 += __shfl_xor_sync(0xffffffffu, l0, 2);
    l1 += __shfl_xor_sync(0xffffffffu, l1, 1);
    l1 += __shfl_xor_sync(0xffffffffu, l1, 2);
    float i0 = 1.f / l0, i1 = 1.f / l1;

    int r = wm * 16 + (lane >> 2);
    #pragma unroll
    for (int nt = 0; nt < 8; nt++) {
        int c = nt * 8 + (lane & 3) * 2;
        size_t ob = ((size_t)b * SEQ + q0 + r) * DIMC + h * HD + c;
        unsigned hw, lw;
        split2(oacc[nt][0] * i0, oacc[nt][1] * i0, hw, lw);
        *(unsigned*)(g_ahi + ob) = hw;
        *(unsigned*)(g_alo + ob) = lw;
        split2(oacc[nt][2] * i1, oacc[nt][3] * i1, hw, lw);
        *(unsigned*)(g_ahi + ob + (size_t)8 * DIMC) = hw;
        *(unsigned*)(g_alo + ob + (size_t)8 * DIMC) = lw;
    }
}

// ---------------- host ----------------
extern "C" void kernel_launch(void* const* d_in, const int* in_sizes, int n_in,
                              void* d_out, int out_size) {
    const float* x      = (const float*)d_in[0];
    const float* w_qkv  = (const float*)d_in[1];
    const float* w_proj = (const float*)d_in[2];
    const float* b_proj = (const float*)d_in[3];
    float* out = (float*)d_out;

    __nv_bfloat16 *xhi, *xlo, *wqh, *wql, *wph, *wpl, *ahi, *alo;
    cudaGetSymbolAddress((void**)&xhi, g_xhi);    cudaGetSymbolAddress((void**)&xlo, g_xlo);
    cudaGetSymbolAddress((void**)&wqh, g_wqt_hi); cudaGetSymbolAddress((void**)&wql, g_wqt_lo);
    cudaGetSymbolAddress((void**)&wph, g_wpt_hi); cudaGetSymbolAddress((void**)&wpl, g_wpt_lo);
    cudaGetSymbolAddress((void**)&ahi, g_ahi);    cudaGetSymbolAddress((void**)&alo, g_alo);

    const int GEMM_SMEM = 2 * 40960 + 256;          // 82176
    const int ATTN_SMEM = 16384 + 2 * 24576 + 1024; // 66560
    cudaFuncSetAttribute(gemm_mma<0>, cudaFuncAttributeMaxDynamicSharedMemorySize, GEMM_SMEM);
    cudaFuncSetAttribute(gemm_mma<1>, cudaFuncAttributeMaxDynamicSharedMemorySize, GEMM_SMEM);
    cudaFuncSetAttribute(attn_mma, cudaFuncAttributeMaxDynamicSharedMemorySize, ATTN_SMEM);

    int nx = MTOT * DIMC;
    split_plain<<<(nx + 255) / 256, 256>>>(x, xhi, xlo, nx);
    split_wT<<<(3 * DIMC * DIMC + 255) / 256, 256>>>(w_qkv, wqh, wql, DIMC, 3 * DIMC);
    split_wT<<<(DIMC * DIMC + 255) / 256, 256>>>(w_proj, wph, wpl, DIMC, DIMC);

    gemm_mma<0><<<dim3(9, 128), 256, GEMM_SMEM>>>(xhi, xlo, wqh, wql, nullptr, nullptr, 0);
    attn_mma<<<dim3(SEQ / 128, BH), 256, ATTN_SMEM>>>();
    gemm_mma<1><<<dim3(3, 128), 256, GEMM_SMEM>>>(ahi, alo, wph, wpl, out, b_proj, DIMC);
}